// round 8
// baseline (speedup 1.0000x reference)
#include <cuda_runtime.h>
#include <cuda_bf16.h>
#include <cstdint>

#define D1 256
#define D2 128
#define K_DIM 256

static const int MAX_N = 100000;
static const int MAX_E = 1600000;

// fp32 scratch
__device__ float g_y1[MAX_N * D1];
__device__ float g_z1[MAX_N * D1];
__device__ float g_y2[MAX_N * D2];
__device__ float g_z2[MAX_N * D2];
__device__ float g_deg[MAX_N];
// bf16 split scratch
__device__ __nv_bfloat16 g_xhi[MAX_N * D1];
__device__ __nv_bfloat16 g_xlo[MAX_N * D1];
__device__ __nv_bfloat16 g_hhi[MAX_N * D1];
__device__ __nv_bfloat16 g_hlo[MAX_N * D1];
// weight splits
__device__ __nv_bfloat16 g_w[6 * 65536];
// CSR
__device__ int g_rowptr[MAX_N];
__device__ int g_cursor[MAX_N];
__device__ int g_csr[MAX_E];
__device__ int g_bsum[128];
__device__ int g_boff[128];

#define SCAN_BLK 1024

// ---------------------------------------------------------------------------
__device__ __forceinline__ uint32_t smem_to_u32(const void* p) {
    uint32_t a;
    asm("{ .reg .u64 t; cvta.to.shared.u64 t, %1; cvt.u32.u64 %0, t; }"
        : "=r"(a) : "l"(p));
    return a;
}

__device__ __forceinline__ void cp_async16(uint32_t saddr, const void* gaddr, uint32_t n) {
    asm volatile("cp.async.cg.shared.global [%0], [%1], 16, %2;"
                 :: "r"(saddr), "l"(gaddr), "r"(n) : "memory");
}

__device__ __forceinline__ void mma_bf16(float* c, const uint32_t* a, const uint32_t* b) {
    asm volatile(
        "mma.sync.aligned.m16n8k16.row.col.f32.bf16.bf16.f32 "
        "{%0,%1,%2,%3}, {%4,%5,%6,%7}, {%8,%9}, {%0,%1,%2,%3};"
        : "+f"(c[0]), "+f"(c[1]), "+f"(c[2]), "+f"(c[3])
        : "r"(a[0]), "r"(a[1]), "r"(a[2]), "r"(a[3]), "r"(b[0]), "r"(b[1]));
}

#define LDSM_X4(r, addr) \
    asm volatile("ldmatrix.sync.aligned.m8n8.x4.shared.b16 {%0,%1,%2,%3}, [%4];" \
                 : "=r"((r)[0]), "=r"((r)[1]), "=r"((r)[2]), "=r"((r)[3]) \
                 : "r"(addr))

// ---------------------------------------------------------------------------
// bf16x3 GEMM, 128 rows x 256 cols per CTA, 512 threads (16 warps, 4/SMSP),
// warp tile 32x64, 3-stage cp.async pipeline, 1 bar per K-chunk.
// ---------------------------------------------------------------------------
#define ROWB 80
#define AHI_OFF 0
#define ALO_OFF (128 * ROWB)
#define BHI_OFF (256 * ROWB)
#define BLO_OFF (512 * ROWB)
#define STAGE_SZ (768 * ROWB)          // 61440
#define GEMM_SMEM (3 * STAGE_SZ)       // 184320

__global__ __launch_bounds__(512, 1)
void gemm3(const __nv_bfloat16* __restrict__ Ahi,
           const __nv_bfloat16* __restrict__ Alo,
           const __nv_bfloat16* __restrict__ Whi,   // 256 rows x 256
           const __nv_bfloat16* __restrict__ Wlo,
           float* __restrict__ outA, int ldA, const float* __restrict__ biasA,
           float* __restrict__ outB, int ldB, const float* __restrict__ biasB,
           int M) {
    extern __shared__ char smem[];
    const uint32_t sbase = smem_to_u32(smem);
    const int tid = threadIdx.x;
    const int wid = tid >> 5, lane = tid & 31;
    const int wr = wid >> 2;   // 0..3 : 32-row block
    const int wc = wid & 3;    // 0..3 : 64-col block
    const int m0 = (int)blockIdx.x * 128;

    float acc[2][8][4];
#pragma unroll
    for (int i = 0; i < 2; i++)
#pragma unroll
        for (int j = 0; j < 8; j++)
#pragma unroll
            for (int k = 0; k < 4; k++) acc[i][j][k] = 0.0f;

    auto issue = [&](int c, int stage) {
        const uint32_t s0 = sbase + (uint32_t)stage * STAGE_SZ;
        const int ke = c * 32;
        // A hi/lo: 128 rows x 4 chunks = 512 chunks, 1 per thread each
        {
            int row = tid >> 2, cc = tid & 3;
            int gm = m0 + row;
            uint32_t p = (gm < M) ? 16u : 0u;
            const size_t goff = (size_t)gm * K_DIM + ke + cc * 8;
            cp_async16(s0 + AHI_OFF + row * ROWB + cc * 16, Ahi + goff, p);
            cp_async16(s0 + ALO_OFF + row * ROWB + cc * 16, Alo + goff, p);
        }
        // B hi/lo: 256 rows x 4 chunks = 1024 chunks, 2 per thread each
#pragma unroll
        for (int i = 0; i < 2; i++) {
            int id = tid + i * 512;
            int row = id >> 2, cc = id & 3;
            const size_t goff = (size_t)row * K_DIM + ke + cc * 8;
            cp_async16(s0 + BHI_OFF + row * ROWB + cc * 16, Whi + goff, 16u);
            cp_async16(s0 + BLO_OFF + row * ROWB + cc * 16, Wlo + goff, 16u);
        }
        asm volatile("cp.async.commit_group;" ::: "memory");
    };

    issue(0, 0);
    issue(1, 1);

    for (int c = 0; c < 8; c++) {
        asm volatile("cp.async.wait_group 1;" ::: "memory");
        __syncthreads();
        if (c + 2 < 8) issue(c + 2, (c + 2) % 3);

        const uint32_t s0 = sbase + (uint32_t)(c % 3) * STAGE_SZ;
#pragma unroll
        for (int s = 0; s < 2; s++) {
            const uint32_t aoff = s0 + (uint32_t)(wr * 32 + (lane & 15)) * ROWB
                                  + ((lane >> 4) << 4) + s * 32;
            const uint32_t boff = s0 + BHI_OFF
                                  + (uint32_t)(wc * 64 + (lane & 7) + ((lane >> 4) << 3)) * ROWB
                                  + (((lane >> 3) & 1) << 4) + s * 32;
            uint32_t ahi[2][4], alo[2][4], bb[4][4];
#pragma unroll
            for (int mi = 0; mi < 2; mi++) {
                LDSM_X4(ahi[mi], aoff + AHI_OFF + mi * (16 * ROWB));
                LDSM_X4(alo[mi], aoff + ALO_OFF + mi * (16 * ROWB));
            }
#pragma unroll
            for (int p = 0; p < 4; p++) LDSM_X4(bb[p], boff + p * (16 * ROWB));
#pragma unroll
            for (int mi = 0; mi < 2; mi++)
#pragma unroll
                for (int p = 0; p < 4; p++) {
                    mma_bf16(acc[mi][2 * p],     ahi[mi], &bb[p][0]);
                    mma_bf16(acc[mi][2 * p + 1], ahi[mi], &bb[p][2]);
                    mma_bf16(acc[mi][2 * p],     alo[mi], &bb[p][0]);
                    mma_bf16(acc[mi][2 * p + 1], alo[mi], &bb[p][2]);
                }
#pragma unroll
            for (int p = 0; p < 4; p++) LDSM_X4(bb[p], boff + (BLO_OFF - BHI_OFF) + p * (16 * ROWB));
#pragma unroll
            for (int mi = 0; mi < 2; mi++)
#pragma unroll
                for (int p = 0; p < 4; p++) {
                    mma_bf16(acc[mi][2 * p],     ahi[mi], &bb[p][0]);
                    mma_bf16(acc[mi][2 * p + 1], ahi[mi], &bb[p][2]);
                }
        }
    }

    const bool isB = (wc >= 2);
    float* out = isB ? outB : outA;
    const int ld = isB ? ldB : ldA;
    const float* bias = isB ? biasB : biasA;
    const int cbase = wc * 64 - (isB ? 128 : 0);

#pragma unroll
    for (int mi = 0; mi < 2; mi++) {
        int r0 = m0 + wr * 32 + mi * 16 + (lane >> 2);
        int r1 = r0 + 8;
#pragma unroll
        for (int ni = 0; ni < 8; ni++) {
            int col = cbase + ni * 8 + 2 * (lane & 3);
            float bx = 0.f, by = 0.f;
            if (bias) { bx = __ldg(bias + col); by = __ldg(bias + col + 1); }
            if (r0 < M)
                *(float2*)(out + (size_t)r0 * ld + col) =
                    make_float2(acc[mi][ni][0] + bx, acc[mi][ni][1] + by);
            if (r1 < M)
                *(float2*)(out + (size_t)r1 * ld + col) =
                    make_float2(acc[mi][ni][2] + bx, acc[mi][ni][3] + by);
        }
    }
}

// ---------------------------------------------------------------------------
// splits
// ---------------------------------------------------------------------------
__device__ __forceinline__ void split1(float v, __nv_bfloat16& h, __nv_bfloat16& l) {
    h = __float2bfloat16(v);
    l = __float2bfloat16(v - __bfloat162float(h));
}

__global__ void split_kernel(const float* __restrict__ in,
                             __nv_bfloat16* __restrict__ hi,
                             __nv_bfloat16* __restrict__ lo, int n4) {
    int i = blockIdx.x * blockDim.x + threadIdx.x;
    if (i >= n4) return;
    float4 v = ((const float4*)in)[i];
    __nv_bfloat16 h0, h1, h2, h3, l0, l1, l2, l3;
    split1(v.x, h0, l0); split1(v.y, h1, l1);
    split1(v.z, h2, l2); split1(v.w, h3, l3);
    ((__nv_bfloat162*)hi)[2 * i]     = __nv_bfloat162(h0, h1);
    ((__nv_bfloat162*)hi)[2 * i + 1] = __nv_bfloat162(h2, h3);
    ((__nv_bfloat162*)lo)[2 * i]     = __nv_bfloat162(l0, l1);
    ((__nv_bfloat162*)lo)[2 * i + 1] = __nv_bfloat162(l2, l3);
}

__global__ void wsplit_all(const float* __restrict__ W1l, const float* __restrict__ W1r,
                           const float* __restrict__ W2l, const float* __restrict__ W2r,
                           __nv_bfloat16* __restrict__ w) {
    int i = blockIdx.x * blockDim.x + threadIdx.x;
    const float* src;
    __nv_bfloat16 *hi, *lo;
    int base;
    if (i < 16384)      { src = W1l; base = i;          hi = w;               lo = w + 65536; }
    else if (i < 32768) { src = W1r; base = i - 16384;  hi = w + 2 * 65536;   lo = w + 3 * 65536; }
    else if (i < 40960) { src = W2l; base = i - 32768;  hi = w + 4 * 65536;   lo = w + 5 * 65536; }
    else if (i < 49152) { src = W2r; base = i - 40960;  hi = w + 4 * 65536 + 32768; lo = w + 5 * 65536 + 32768; }
    else return;
    float4 v = ((const float4*)src)[base];
    __nv_bfloat16 h0, h1, h2, h3, l0, l1, l2, l3;
    split1(v.x, h0, l0); split1(v.y, h1, l1);
    split1(v.z, h2, l2); split1(v.w, h3, l3);
    ((__nv_bfloat162*)hi)[2 * base]     = __nv_bfloat162(h0, h1);
    ((__nv_bfloat162*)hi)[2 * base + 1] = __nv_bfloat162(h2, h3);
    ((__nv_bfloat162*)lo)[2 * base]     = __nv_bfloat162(l0, l1);
    ((__nv_bfloat162*)lo)[2 * base + 1] = __nv_bfloat162(l2, l3);
}

// ---------------------------------------------------------------------------
// degree + CSR build
// ---------------------------------------------------------------------------
__global__ void deg_kernel(const int* __restrict__ dst, float* __restrict__ deg, int E) {
    int i = blockIdx.x * blockDim.x + threadIdx.x;
    if (i < E) atomicAdd(&deg[dst[i]], 1.0f);
}

__global__ void scan_part(const float* __restrict__ deg, int* __restrict__ bsum, int N) {
    __shared__ int sm[256];
    int b = blockIdx.x, t = threadIdx.x;
    int s = 0;
#pragma unroll
    for (int k = 0; k < 4; k++) {
        int i = b * SCAN_BLK + t * 4 + k;
        if (i < N) s += (int)deg[i];
    }
    sm[t] = s;
    __syncthreads();
    for (int o = 128; o > 0; o >>= 1) {
        if (t < o) sm[t] += sm[t + o];
        __syncthreads();
    }
    if (t == 0) bsum[b] = sm[0];
}

__global__ void scan_sums(const int* __restrict__ bsum, int* __restrict__ boff, int nb) {
    __shared__ int sm[128];
    int t = threadIdx.x;
    sm[t] = (t < nb) ? bsum[t] : 0;
    __syncthreads();
    for (int o = 1; o < 128; o <<= 1) {
        int v = (t >= o) ? sm[t - o] : 0;
        __syncthreads();
        sm[t] += v;
        __syncthreads();
    }
    if (t < nb) boff[t] = (t == 0) ? 0 : sm[t - 1];
}

__global__ void scan_write(const float* __restrict__ deg, const int* __restrict__ boff,
                           int* __restrict__ rowptr, int* __restrict__ cursor, int N) {
    __shared__ int sm[256];
    int b = blockIdx.x, t = threadIdx.x;
    int d[4];
    int s = 0;
#pragma unroll
    for (int k = 0; k < 4; k++) {
        int i = b * SCAN_BLK + t * 4 + k;
        d[k] = (i < N) ? (int)deg[i] : 0;
        s += d[k];
    }
    sm[t] = s;
    __syncthreads();
    for (int o = 1; o < 256; o <<= 1) {
        int v = (t >= o) ? sm[t - o] : 0;
        __syncthreads();
        sm[t] += v;
        __syncthreads();
    }
    int off = boff[b] + ((t == 0) ? 0 : sm[t - 1]);
#pragma unroll
    for (int k = 0; k < 4; k++) {
        int i = b * SCAN_BLK + t * 4 + k;
        if (i < N) { rowptr[i] = off; cursor[i] = off; }
        off += d[k];
    }
}

__global__ void fill_csr(const int* __restrict__ src, const int* __restrict__ dst,
                         int* __restrict__ cursor, int* __restrict__ csr, int E) {
    int i = blockIdx.x * blockDim.x + threadIdx.x;
    if (i >= E) return;
    int pos = atomicAdd(&cursor[dst[i]], 1);
    csr[pos] = src[i];
}

// ---------------------------------------------------------------------------
// CSR gathers (combine fused)
// ---------------------------------------------------------------------------
__global__ void gather1(const float* __restrict__ y, const float* __restrict__ z,
                        const int* __restrict__ rowptr, const int* __restrict__ csr,
                        const float* __restrict__ deg,
                        __nv_bfloat16* __restrict__ hhi, __nv_bfloat16* __restrict__ hlo,
                        int N) {
    int gw = (blockIdx.x * blockDim.x + threadIdx.x) >> 5;
    int lane = threadIdx.x & 31;
    int node = gw >> 1;
    int c0 = (gw & 1) * 128;
    if (node >= N) return;

    int start = rowptr[node];
    float degf = deg[node];
    int cnt = (int)degf;
    float4 acc = make_float4(0.f, 0.f, 0.f, 0.f);
    for (int j0 = 0; j0 < cnt; j0 += 32) {
        int m = min(32, cnt - j0);
        int sid = (lane < m) ? csr[start + j0 + lane] : 0;
        for (int t = 0; t < m; t++) {
            int sN = __shfl_sync(0xffffffff, sid, t);
            float4 v = *(const float4*)(y + (size_t)sN * D1 + c0 + lane * 4);
            acc.x += v.x; acc.y += v.y; acc.z += v.z; acc.w += v.w;
        }
    }
    float sc = 1.0f / fmaxf(degf, 1.0f);
    float4 zz = *(const float4*)(z + (size_t)node * D1 + c0 + lane * 4);
    float4 r;
    r.x = fmaxf(acc.x * sc + zz.x, 0.f);
    r.y = fmaxf(acc.y * sc + zz.y, 0.f);
    r.z = fmaxf(acc.z * sc + zz.z, 0.f);
    r.w = fmaxf(acc.w * sc + zz.w, 0.f);
    __nv_bfloat16 h0, h1, h2, h3, l0, l1, l2, l3;
    split1(r.x, h0, l0); split1(r.y, h1, l1);
    split1(r.z, h2, l2); split1(r.w, h3, l3);
    size_t o = (size_t)node * D1 + c0 + lane * 4;
    *(__nv_bfloat162*)(hhi + o)     = __nv_bfloat162(h0, h1);
    *(__nv_bfloat162*)(hhi + o + 2) = __nv_bfloat162(h2, h3);
    *(__nv_bfloat162*)(hlo + o)     = __nv_bfloat162(l0, l1);
    *(__nv_bfloat162*)(hlo + o + 2) = __nv_bfloat162(l2, l3);
}

__global__ void gather2(const float* __restrict__ y, const float* __restrict__ z,
                        const int* __restrict__ rowptr, const int* __restrict__ csr,
                        const float* __restrict__ deg,
                        float* __restrict__ out, int N) {
    int node = (blockIdx.x * blockDim.x + threadIdx.x) >> 5;
    int lane = threadIdx.x & 31;
    if (node >= N) return;

    int start = rowptr[node];
    float degf = deg[node];
    int cnt = (int)degf;
    float4 acc = make_float4(0.f, 0.f, 0.f, 0.f);
    for (int j0 = 0; j0 < cnt; j0 += 32) {
        int m = min(32, cnt - j0);
        int sid = (lane < m) ? csr[start + j0 + lane] : 0;
        for (int t = 0; t < m; t++) {
            int sN = __shfl_sync(0xffffffff, sid, t);
            float4 v = *(const float4*)(y + (size_t)sN * D2 + lane * 4);
            acc.x += v.x; acc.y += v.y; acc.z += v.z; acc.w += v.w;
        }
    }
    float sc = 1.0f / fmaxf(degf, 1.0f);
    float4 zz = *(const float4*)(z + (size_t)node * D2 + lane * 4);
    *(float4*)(out + (size_t)node * D2 + lane * 4) =
        make_float4(acc.x * sc + zz.x, acc.y * sc + zz.y,
                    acc.z * sc + zz.z, acc.w * sc + zz.w);
}

// ---------------------------------------------------------------------------
extern "C" void kernel_launch(void* const* d_in, const int* in_sizes, int n_in,
                              void* d_out, int out_size) {
    const float* x    = (const float*)d_in[0];
    const int* eidx   = (const int*)d_in[1];
    const float* W1l  = (const float*)d_in[2];
    const float* b1   = (const float*)d_in[3];
    const float* W1r  = (const float*)d_in[4];
    const float* W2l  = (const float*)d_in[5];
    const float* b2   = (const float*)d_in[6];
    const float* W2r  = (const float*)d_in[7];
    float* out = (float*)d_out;

    const int N = in_sizes[0] / D1;
    const int E = in_sizes[1] / 2;
    const int* src = eidx;
    const int* dst = eidx + E;

    float *y1, *z1, *y2, *z2, *deg;
    __nv_bfloat16 *xhi, *xlo, *hhi, *hlo, *w;
    int *rowptr, *cursor, *csr, *bsum, *boff;
    cudaGetSymbolAddress((void**)&y1,   g_y1);
    cudaGetSymbolAddress((void**)&z1,   g_z1);
    cudaGetSymbolAddress((void**)&y2,   g_y2);
    cudaGetSymbolAddress((void**)&z2,   g_z2);
    cudaGetSymbolAddress((void**)&deg,  g_deg);
    cudaGetSymbolAddress((void**)&xhi,  g_xhi);
    cudaGetSymbolAddress((void**)&xlo,  g_xlo);
    cudaGetSymbolAddress((void**)&hhi,  g_hhi);
    cudaGetSymbolAddress((void**)&hlo,  g_hlo);
    cudaGetSymbolAddress((void**)&w,    g_w);
    cudaGetSymbolAddress((void**)&rowptr, g_rowptr);
    cudaGetSymbolAddress((void**)&cursor, g_cursor);
    cudaGetSymbolAddress((void**)&csr,    g_csr);
    cudaGetSymbolAddress((void**)&bsum,   g_bsum);
    cudaGetSymbolAddress((void**)&boff,   g_boff);

    __nv_bfloat16* w1l_hi = w;
    __nv_bfloat16* w1l_lo = w + 65536;
    __nv_bfloat16* w1r_hi = w + 2 * 65536;
    __nv_bfloat16* w1r_lo = w + 3 * 65536;
    __nv_bfloat16* w2_hi  = w + 4 * 65536;   // [W2l ; W2r] stacked
    __nv_bfloat16* w2_lo  = w + 5 * 65536;

    cudaFuncSetAttribute(gemm3, cudaFuncAttributeMaxDynamicSharedMemorySize, GEMM_SMEM);

    const int mb = (N + 127) / 128;
    const int nb = (N + SCAN_BLK - 1) / SCAN_BLK;

    cudaMemsetAsync(deg, 0, (size_t)N * sizeof(float));
    deg_kernel<<<(E + 255) / 256, 256>>>(dst, deg, E);                            // k1
    split_kernel<<<(N * (D1 / 4) + 255) / 256, 256>>>(x, xhi, xlo, N * (D1 / 4)); // k2
    wsplit_all<<<(49152 + 255) / 256, 256>>>(W1l, W1r, W2l, W2r, w);              // k3
    // k4 ← ncu-profiled slot: the GEMM
    gemm3<<<mb, 512, GEMM_SMEM>>>(xhi, xlo, w1l_hi, w1l_lo,
                                  y1, D1, nullptr, y1 + 128, D1, nullptr, N);     // k4
    scan_part<<<nb, 256>>>(deg, bsum, N);                                         // k5
    scan_sums<<<1, 128>>>(bsum, boff, nb);                                        // k6
    scan_write<<<nb, 256>>>(deg, boff, rowptr, cursor, N);                        // k7
    fill_csr<<<(E + 255) / 256, 256>>>(src, dst, cursor, csr, E);                 // k8
    gemm3<<<mb, 512, GEMM_SMEM>>>(xhi, xlo, w1r_hi, w1r_lo,
                                  z1, D1, b1, z1 + 128, D1, b1 + 128, N);         // k9
    gather1<<<(2 * N * 32 + 255) / 256, 256>>>(y1, z1, rowptr, csr, deg, hhi, hlo, N); // k10
    gemm3<<<mb, 512, GEMM_SMEM>>>(hhi, hlo, w2_hi, w2_lo,
                                  y2, D2, nullptr, z2, D2, b2, N);                // k11
    gather2<<<(N * 32 + 255) / 256, 256>>>(y2, z2, rowptr, csr, deg, out, N);     // k12
}

// round 9
// speedup vs baseline: 1.0058x; 1.0058x over previous
#include <cuda_runtime.h>
#include <cuda_bf16.h>
#include <cstdint>

#define D1 256
#define D2 128
#define K_DIM 256

static const int MAX_N = 100000;
static const int MAX_E = 1600000;

// fp32 scratch
__device__ float g_y1[MAX_N * D1];
__device__ float g_z1[MAX_N * D1];
__device__ float g_y2[MAX_N * D2];
__device__ float g_z2[MAX_N * D2];
__device__ float g_deg[MAX_N];
// bf16 split scratch
__device__ __nv_bfloat16 g_xhi[MAX_N * D1];
__device__ __nv_bfloat16 g_xlo[MAX_N * D1];
__device__ __nv_bfloat16 g_hhi[MAX_N * D1];
__device__ __nv_bfloat16 g_hlo[MAX_N * D1];
// weight splits
__device__ __nv_bfloat16 g_w[6 * 65536];
// CSR
__device__ int g_rowptr[MAX_N];
__device__ int g_cursor[MAX_N];
__device__ int g_csr[MAX_E];
__device__ int g_bsum[128];
__device__ int g_boff[128];

#define SCAN_BLK 1024

// ---------------------------------------------------------------------------
__device__ __forceinline__ uint32_t smem_to_u32(const void* p) {
    uint32_t a;
    asm("{ .reg .u64 t; cvta.to.shared.u64 t, %1; cvt.u32.u64 %0, t; }"
        : "=r"(a) : "l"(p));
    return a;
}

__device__ __forceinline__ void cp_async16(uint32_t saddr, const void* gaddr, uint32_t n) {
    asm volatile("cp.async.cg.shared.global [%0], [%1], 16, %2;"
                 :: "r"(saddr), "l"(gaddr), "r"(n) : "memory");
}

__device__ __forceinline__ void mma_bf16(float* c, const uint32_t* a, const uint32_t* b) {
    asm volatile(
        "mma.sync.aligned.m16n8k16.row.col.f32.bf16.bf16.f32 "
        "{%0,%1,%2,%3}, {%4,%5,%6,%7}, {%8,%9}, {%0,%1,%2,%3};"
        : "+f"(c[0]), "+f"(c[1]), "+f"(c[2]), "+f"(c[3])
        : "r"(a[0]), "r"(a[1]), "r"(a[2]), "r"(a[3]), "r"(b[0]), "r"(b[1]));
}

#define LDSM_X4(r, addr) \
    asm volatile("ldmatrix.sync.aligned.m8n8.x4.shared.b16 {%0,%1,%2,%3}, [%4];" \
                 : "=r"((r)[0]), "=r"((r)[1]), "=r"((r)[2]), "=r"((r)[3]) \
                 : "r"(addr))

// ---------------------------------------------------------------------------
// bf16x3 GEMM, 128 rows x 256 cols per CTA, 512 threads (16 warps, 4/SMSP),
// warp tile 32x64, 3-stage cp.async pipeline, 1 bar per K-chunk.
// ---------------------------------------------------------------------------
#define ROWB 80
#define AHI_OFF 0
#define ALO_OFF (128 * ROWB)
#define BHI_OFF (256 * ROWB)
#define BLO_OFF (512 * ROWB)
#define STAGE_SZ (768 * ROWB)          // 61440
#define GEMM_SMEM (3 * STAGE_SZ)       // 184320

__global__ __launch_bounds__(512, 1)
void gemm3(const __nv_bfloat16* __restrict__ Ahi,
           const __nv_bfloat16* __restrict__ Alo,
           const __nv_bfloat16* __restrict__ Whi,   // 256 rows x 256
           const __nv_bfloat16* __restrict__ Wlo,
           float* __restrict__ outA, int ldA, const float* __restrict__ biasA,
           float* __restrict__ outB, int ldB, const float* __restrict__ biasB,
           int M) {
    extern __shared__ char smem[];
    const uint32_t sbase = smem_to_u32(smem);
    const int tid = threadIdx.x;
    const int wid = tid >> 5, lane = tid & 31;
    const int wr = wid >> 2;   // 0..3 : 32-row block
    const int wc = wid & 3;    // 0..3 : 64-col block
    const int m0 = (int)blockIdx.x * 128;

    float acc[2][8][4];
#pragma unroll
    for (int i = 0; i < 2; i++)
#pragma unroll
        for (int j = 0; j < 8; j++)
#pragma unroll
            for (int k = 0; k < 4; k++) acc[i][j][k] = 0.0f;

    auto issue = [&](int c, int stage) {
        const uint32_t s0 = sbase + (uint32_t)stage * STAGE_SZ;
        const int ke = c * 32;
        // A hi/lo: 128 rows x 4 chunks = 512 chunks, 1 per thread each
        {
            int row = tid >> 2, cc = tid & 3;
            int gm = m0 + row;
            uint32_t p = (gm < M) ? 16u : 0u;
            const size_t goff = (size_t)gm * K_DIM + ke + cc * 8;
            cp_async16(s0 + AHI_OFF + row * ROWB + cc * 16, Ahi + goff, p);
            cp_async16(s0 + ALO_OFF + row * ROWB + cc * 16, Alo + goff, p);
        }
        // B hi/lo: 256 rows x 4 chunks = 1024 chunks, 2 per thread each
#pragma unroll
        for (int i = 0; i < 2; i++) {
            int id = tid + i * 512;
            int row = id >> 2, cc = id & 3;
            const size_t goff = (size_t)row * K_DIM + ke + cc * 8;
            cp_async16(s0 + BHI_OFF + row * ROWB + cc * 16, Whi + goff, 16u);
            cp_async16(s0 + BLO_OFF + row * ROWB + cc * 16, Wlo + goff, 16u);
        }
        asm volatile("cp.async.commit_group;" ::: "memory");
    };

    issue(0, 0);
    issue(1, 1);

    for (int c = 0; c < 8; c++) {
        asm volatile("cp.async.wait_group 1;" ::: "memory");
        __syncthreads();
        if (c + 2 < 8) issue(c + 2, (c + 2) % 3);

        const uint32_t s0 = sbase + (uint32_t)(c % 3) * STAGE_SZ;
#pragma unroll
        for (int s = 0; s < 2; s++) {
            const uint32_t aoff = s0 + (uint32_t)(wr * 32 + (lane & 15)) * ROWB
                                  + ((lane >> 4) << 4) + s * 32;
            const uint32_t boff = s0 + BHI_OFF
                                  + (uint32_t)(wc * 64 + (lane & 7) + ((lane >> 4) << 3)) * ROWB
                                  + (((lane >> 3) & 1) << 4) + s * 32;
            uint32_t ahi[2][4], alo[2][4], bb[4][4];
#pragma unroll
            for (int mi = 0; mi < 2; mi++) {
                LDSM_X4(ahi[mi], aoff + AHI_OFF + mi * (16 * ROWB));
                LDSM_X4(alo[mi], aoff + ALO_OFF + mi * (16 * ROWB));
            }
#pragma unroll
            for (int p = 0; p < 4; p++) LDSM_X4(bb[p], boff + p * (16 * ROWB));
#pragma unroll
            for (int mi = 0; mi < 2; mi++)
#pragma unroll
                for (int p = 0; p < 4; p++) {
                    mma_bf16(acc[mi][2 * p],     ahi[mi], &bb[p][0]);
                    mma_bf16(acc[mi][2 * p + 1], ahi[mi], &bb[p][2]);
                    mma_bf16(acc[mi][2 * p],     alo[mi], &bb[p][0]);
                    mma_bf16(acc[mi][2 * p + 1], alo[mi], &bb[p][2]);
                }
#pragma unroll
            for (int p = 0; p < 4; p++) LDSM_X4(bb[p], boff + (BLO_OFF - BHI_OFF) + p * (16 * ROWB));
#pragma unroll
            for (int mi = 0; mi < 2; mi++)
#pragma unroll
                for (int p = 0; p < 4; p++) {
                    mma_bf16(acc[mi][2 * p],     ahi[mi], &bb[p][0]);
                    mma_bf16(acc[mi][2 * p + 1], ahi[mi], &bb[p][2]);
                }
        }
    }

    const bool isB = (wc >= 2);
    float* out = isB ? outB : outA;
    const int ld = isB ? ldB : ldA;
    const float* bias = isB ? biasB : biasA;
    const int cbase = wc * 64 - (isB ? 128 : 0);

#pragma unroll
    for (int mi = 0; mi < 2; mi++) {
        int r0 = m0 + wr * 32 + mi * 16 + (lane >> 2);
        int r1 = r0 + 8;
#pragma unroll
        for (int ni = 0; ni < 8; ni++) {
            int col = cbase + ni * 8 + 2 * (lane & 3);
            float bx = 0.f, by = 0.f;
            if (bias) { bx = __ldg(bias + col); by = __ldg(bias + col + 1); }
            if (r0 < M)
                *(float2*)(out + (size_t)r0 * ld + col) =
                    make_float2(acc[mi][ni][0] + bx, acc[mi][ni][1] + by);
            if (r1 < M)
                *(float2*)(out + (size_t)r1 * ld + col) =
                    make_float2(acc[mi][ni][2] + bx, acc[mi][ni][3] + by);
        }
    }
}

// ---------------------------------------------------------------------------
// splits
// ---------------------------------------------------------------------------
__device__ __forceinline__ void split1(float v, __nv_bfloat16& h, __nv_bfloat16& l) {
    h = __float2bfloat16(v);
    l = __float2bfloat16(v - __bfloat162float(h));
}

__global__ void split_kernel(const float* __restrict__ in,
                             __nv_bfloat16* __restrict__ hi,
                             __nv_bfloat16* __restrict__ lo, int n4) {
    int i = blockIdx.x * blockDim.x + threadIdx.x;
    if (i >= n4) return;
    float4 v = ((const float4*)in)[i];
    __nv_bfloat16 h0, h1, h2, h3, l0, l1, l2, l3;
    split1(v.x, h0, l0); split1(v.y, h1, l1);
    split1(v.z, h2, l2); split1(v.w, h3, l3);
    ((__nv_bfloat162*)hi)[2 * i]     = __nv_bfloat162(h0, h1);
    ((__nv_bfloat162*)hi)[2 * i + 1] = __nv_bfloat162(h2, h3);
    ((__nv_bfloat162*)lo)[2 * i]     = __nv_bfloat162(l0, l1);
    ((__nv_bfloat162*)lo)[2 * i + 1] = __nv_bfloat162(l2, l3);
}

__global__ void wsplit_all(const float* __restrict__ W1l, const float* __restrict__ W1r,
                           const float* __restrict__ W2l, const float* __restrict__ W2r,
                           __nv_bfloat16* __restrict__ w) {
    int i = blockIdx.x * blockDim.x + threadIdx.x;
    const float* src;
    __nv_bfloat16 *hi, *lo;
    int base;
    if (i < 16384)      { src = W1l; base = i;          hi = w;               lo = w + 65536; }
    else if (i < 32768) { src = W1r; base = i - 16384;  hi = w + 2 * 65536;   lo = w + 3 * 65536; }
    else if (i < 40960) { src = W2l; base = i - 32768;  hi = w + 4 * 65536;   lo = w + 5 * 65536; }
    else if (i < 49152) { src = W2r; base = i - 40960;  hi = w + 4 * 65536 + 32768; lo = w + 5 * 65536 + 32768; }
    else return;
    float4 v = ((const float4*)src)[base];
    __nv_bfloat16 h0, h1, h2, h3, l0, l1, l2, l3;
    split1(v.x, h0, l0); split1(v.y, h1, l1);
    split1(v.z, h2, l2); split1(v.w, h3, l3);
    ((__nv_bfloat162*)hi)[2 * base]     = __nv_bfloat162(h0, h1);
    ((__nv_bfloat162*)hi)[2 * base + 1] = __nv_bfloat162(h2, h3);
    ((__nv_bfloat162*)lo)[2 * base]     = __nv_bfloat162(l0, l1);
    ((__nv_bfloat162*)lo)[2 * base + 1] = __nv_bfloat162(l2, l3);
}

// ---------------------------------------------------------------------------
// degree + CSR build
// ---------------------------------------------------------------------------
__global__ void deg_kernel(const int* __restrict__ dst, float* __restrict__ deg, int E) {
    int i = blockIdx.x * blockDim.x + threadIdx.x;
    if (i < E) atomicAdd(&deg[dst[i]], 1.0f);
}

__global__ void scan_part(const float* __restrict__ deg, int* __restrict__ bsum, int N) {
    __shared__ int sm[256];
    int b = blockIdx.x, t = threadIdx.x;
    int s = 0;
#pragma unroll
    for (int k = 0; k < 4; k++) {
        int i = b * SCAN_BLK + t * 4 + k;
        if (i < N) s += (int)deg[i];
    }
    sm[t] = s;
    __syncthreads();
    for (int o = 128; o > 0; o >>= 1) {
        if (t < o) sm[t] += sm[t + o];
        __syncthreads();
    }
    if (t == 0) bsum[b] = sm[0];
}

__global__ void scan_sums(const int* __restrict__ bsum, int* __restrict__ boff, int nb) {
    __shared__ int sm[128];
    int t = threadIdx.x;
    sm[t] = (t < nb) ? bsum[t] : 0;
    __syncthreads();
    for (int o = 1; o < 128; o <<= 1) {
        int v = (t >= o) ? sm[t - o] : 0;
        __syncthreads();
        sm[t] += v;
        __syncthreads();
    }
    if (t < nb) boff[t] = (t == 0) ? 0 : sm[t - 1];
}

__global__ void scan_write(const float* __restrict__ deg, const int* __restrict__ boff,
                           int* __restrict__ rowptr, int* __restrict__ cursor, int N) {
    __shared__ int sm[256];
    int b = blockIdx.x, t = threadIdx.x;
    int d[4];
    int s = 0;
#pragma unroll
    for (int k = 0; k < 4; k++) {
        int i = b * SCAN_BLK + t * 4 + k;
        d[k] = (i < N) ? (int)deg[i] : 0;
        s += d[k];
    }
    sm[t] = s;
    __syncthreads();
    for (int o = 1; o < 256; o <<= 1) {
        int v = (t >= o) ? sm[t - o] : 0;
        __syncthreads();
        sm[t] += v;
        __syncthreads();
    }
    int off = boff[b] + ((t == 0) ? 0 : sm[t - 1]);
#pragma unroll
    for (int k = 0; k < 4; k++) {
        int i = b * SCAN_BLK + t * 4 + k;
        if (i < N) { rowptr[i] = off; cursor[i] = off; }
        off += d[k];
    }
}

__global__ void fill_csr(const int* __restrict__ src, const int* __restrict__ dst,
                         int* __restrict__ cursor, int* __restrict__ csr, int E) {
    int i = blockIdx.x * blockDim.x + threadIdx.x;
    if (i >= E) return;
    int pos = atomicAdd(&cursor[dst[i]], 1);
    csr[pos] = src[i];
}

// ---------------------------------------------------------------------------
// CSR gathers (combine fused)
// ---------------------------------------------------------------------------
__global__ void gather1(const float* __restrict__ y, const float* __restrict__ z,
                        const int* __restrict__ rowptr, const int* __restrict__ csr,
                        const float* __restrict__ deg,
                        __nv_bfloat16* __restrict__ hhi, __nv_bfloat16* __restrict__ hlo,
                        int N) {
    int gw = (blockIdx.x * blockDim.x + threadIdx.x) >> 5;
    int lane = threadIdx.x & 31;
    int node = gw >> 1;
    int c0 = (gw & 1) * 128;
    if (node >= N) return;

    int start = rowptr[node];
    float degf = deg[node];
    int cnt = (int)degf;
    float4 acc = make_float4(0.f, 0.f, 0.f, 0.f);
    for (int j0 = 0; j0 < cnt; j0 += 32) {
        int m = min(32, cnt - j0);
        int sid = (lane < m) ? csr[start + j0 + lane] : 0;
        for (int t = 0; t < m; t++) {
            int sN = __shfl_sync(0xffffffff, sid, t);
            float4 v = *(const float4*)(y + (size_t)sN * D1 + c0 + lane * 4);
            acc.x += v.x; acc.y += v.y; acc.z += v.z; acc.w += v.w;
        }
    }
    float sc = 1.0f / fmaxf(degf, 1.0f);
    float4 zz = *(const float4*)(z + (size_t)node * D1 + c0 + lane * 4);
    float4 r;
    r.x = fmaxf(acc.x * sc + zz.x, 0.f);
    r.y = fmaxf(acc.y * sc + zz.y, 0.f);
    r.z = fmaxf(acc.z * sc + zz.z, 0.f);
    r.w = fmaxf(acc.w * sc + zz.w, 0.f);
    __nv_bfloat16 h0, h1, h2, h3, l0, l1, l2, l3;
    split1(r.x, h0, l0); split1(r.y, h1, l1);
    split1(r.z, h2, l2); split1(r.w, h3, l3);
    size_t o = (size_t)node * D1 + c0 + lane * 4;
    *(__nv_bfloat162*)(hhi + o)     = __nv_bfloat162(h0, h1);
    *(__nv_bfloat162*)(hhi + o + 2) = __nv_bfloat162(h2, h3);
    *(__nv_bfloat162*)(hlo + o)     = __nv_bfloat162(l0, l1);
    *(__nv_bfloat162*)(hlo + o + 2) = __nv_bfloat162(l2, l3);
}

__global__ void gather2(const float* __restrict__ y, const float* __restrict__ z,
                        const int* __restrict__ rowptr, const int* __restrict__ csr,
                        const float* __restrict__ deg,
                        float* __restrict__ out, int N) {
    int node = (blockIdx.x * blockDim.x + threadIdx.x) >> 5;
    int lane = threadIdx.x & 31;
    if (node >= N) return;

    int start = rowptr[node];
    float degf = deg[node];
    int cnt = (int)degf;
    float4 acc = make_float4(0.f, 0.f, 0.f, 0.f);
    for (int j0 = 0; j0 < cnt; j0 += 32) {
        int m = min(32, cnt - j0);
        int sid = (lane < m) ? csr[start + j0 + lane] : 0;
        for (int t = 0; t < m; t++) {
            int sN = __shfl_sync(0xffffffff, sid, t);
            float4 v = *(const float4*)(y + (size_t)sN * D2 + lane * 4);
            acc.x += v.x; acc.y += v.y; acc.z += v.z; acc.w += v.w;
        }
    }
    float sc = 1.0f / fmaxf(degf, 1.0f);
    float4 zz = *(const float4*)(z + (size_t)node * D2 + lane * 4);
    *(float4*)(out + (size_t)node * D2 + lane * 4) =
        make_float4(acc.x * sc + zz.x, acc.y * sc + zz.y,
                    acc.z * sc + zz.z, acc.w * sc + zz.w);
}

// ---------------------------------------------------------------------------
extern "C" void kernel_launch(void* const* d_in, const int* in_sizes, int n_in,
                              void* d_out, int out_size) {
    const float* x    = (const float*)d_in[0];
    const int* eidx   = (const int*)d_in[1];
    const float* W1l  = (const float*)d_in[2];
    const float* b1   = (const float*)d_in[3];
    const float* W1r  = (const float*)d_in[4];
    const float* W2l  = (const float*)d_in[5];
    const float* b2   = (const float*)d_in[6];
    const float* W2r  = (const float*)d_in[7];
    float* out = (float*)d_out;

    const int N = in_sizes[0] / D1;
    const int E = in_sizes[1] / 2;
    const int* src = eidx;
    const int* dst = eidx + E;

    float *y1, *z1, *y2, *z2, *deg;
    __nv_bfloat16 *xhi, *xlo, *hhi, *hlo, *w;
    int *rowptr, *cursor, *csr, *bsum, *boff;
    cudaGetSymbolAddress((void**)&y1,   g_y1);
    cudaGetSymbolAddress((void**)&z1,   g_z1);
    cudaGetSymbolAddress((void**)&y2,   g_y2);
    cudaGetSymbolAddress((void**)&z2,   g_z2);
    cudaGetSymbolAddress((void**)&deg,  g_deg);
    cudaGetSymbolAddress((void**)&xhi,  g_xhi);
    cudaGetSymbolAddress((void**)&xlo,  g_xlo);
    cudaGetSymbolAddress((void**)&hhi,  g_hhi);
    cudaGetSymbolAddress((void**)&hlo,  g_hlo);
    cudaGetSymbolAddress((void**)&w,    g_w);
    cudaGetSymbolAddress((void**)&rowptr, g_rowptr);
    cudaGetSymbolAddress((void**)&cursor, g_cursor);
    cudaGetSymbolAddress((void**)&csr,    g_csr);
    cudaGetSymbolAddress((void**)&bsum,   g_bsum);
    cudaGetSymbolAddress((void**)&boff,   g_boff);

    __nv_bfloat16* w1l_hi = w;
    __nv_bfloat16* w1l_lo = w + 65536;
    __nv_bfloat16* w1r_hi = w + 2 * 65536;
    __nv_bfloat16* w1r_lo = w + 3 * 65536;
    __nv_bfloat16* w2_hi  = w + 4 * 65536;   // [W2l ; W2r] stacked
    __nv_bfloat16* w2_lo  = w + 5 * 65536;

    cudaFuncSetAttribute(gemm3, cudaFuncAttributeMaxDynamicSharedMemorySize, GEMM_SMEM);

    const int mb = (N + 127) / 128;
    const int nb = (N + SCAN_BLK - 1) / SCAN_BLK;

    cudaMemsetAsync(deg, 0, (size_t)N * sizeof(float));
    deg_kernel<<<(E + 255) / 256, 256>>>(dst, deg, E);                            // k1
    split_kernel<<<(N * (D1 / 4) + 255) / 256, 256>>>(x, xhi, xlo, N * (D1 / 4)); // k2
    wsplit_all<<<(49152 + 255) / 256, 256>>>(W1l, W1r, W2l, W2r, w);              // k3
    // k4 ← ncu-profiled slot: the GEMM
    gemm3<<<mb, 512, GEMM_SMEM>>>(xhi, xlo, w1l_hi, w1l_lo,
                                  y1, D1, nullptr, y1 + 128, D1, nullptr, N);     // k4
    scan_part<<<nb, 256>>>(deg, bsum, N);                                         // k5
    scan_sums<<<1, 128>>>(bsum, boff, nb);                                        // k6
    scan_write<<<nb, 256>>>(deg, boff, rowptr, cursor, N);                        // k7
    fill_csr<<<(E + 255) / 256, 256>>>(src, dst, cursor, csr, E);                 // k8
    gemm3<<<mb, 512, GEMM_SMEM>>>(xhi, xlo, w1r_hi, w1r_lo,
                                  z1, D1, b1, z1 + 128, D1, b1 + 128, N);         // k9
    gather1<<<(2 * N * 32 + 255) / 256, 256>>>(y1, z1, rowptr, csr, deg, hhi, hlo, N); // k10
    gemm3<<<mb, 512, GEMM_SMEM>>>(hhi, hlo, w2_hi, w2_lo,
                                  y2, D2, nullptr, z2, D2, b2, N);                // k11
    gather2<<<(N * 32 + 255) / 256, 256>>>(y2, z2, rowptr, csr, deg, out, N);     // k12
}

// round 10
// speedup vs baseline: 1.0840x; 1.0778x over previous
#include <cuda_runtime.h>
#include <cuda_bf16.h>
#include <cstdint>

#define D1 256
#define D2 128
#define K_DIM 256
#define ROWB 80
#define MPAD 100096

static const int MAX_N = 100000;
static const int MAX_E = 1600000;

__device__ float g_y1[MAX_N * D1];
__device__ float g_z1[MAX_N * D1];
__device__ float g_y2[MAX_N * D2];
__device__ float g_z2[MAX_N * D2];
__device__ float g_deg[MAX_N];
// chunk-major padded splits: [8][MPAD][80B]
__device__ uint8_t g_xhi[8ull * MPAD * ROWB];
__device__ uint8_t g_xlo[8ull * MPAD * ROWB];
__device__ uint8_t g_hhi[8ull * MPAD * ROWB];
__device__ uint8_t g_hlo[8ull * MPAD * ROWB];
// stacked weights, chunk-major padded: W1=[W1l;W1r] 512 rows, W2=[W2l;W2r] 256 rows
__device__ uint8_t g_w1hi[8 * 512 * ROWB];
__device__ uint8_t g_w1lo[8 * 512 * ROWB];
__device__ uint8_t g_w2hi[8 * 256 * ROWB];
__device__ uint8_t g_w2lo[8 * 256 * ROWB];
__device__ int g_rowptr[MAX_N];
__device__ int g_cursor[MAX_N];
__device__ int g_csr[MAX_E];
__device__ int g_bsum[128];
__device__ int g_boff[128];

#define SCAN_BLK 1024

__device__ __forceinline__ uint32_t smem_to_u32(const void* p) {
    uint32_t a;
    asm("{ .reg .u64 t; cvta.to.shared.u64 t, %1; cvt.u32.u64 %0, t; }" : "=r"(a) : "l"(p));
    return a;
}
__device__ __forceinline__ void mma_bf16(float* c, const uint32_t* a, const uint32_t* b) {
    asm volatile("mma.sync.aligned.m16n8k16.row.col.f32.bf16.bf16.f32 "
                 "{%0,%1,%2,%3}, {%4,%5,%6,%7}, {%8,%9}, {%0,%1,%2,%3};"
                 : "+f"(c[0]), "+f"(c[1]), "+f"(c[2]), "+f"(c[3])
                 : "r"(a[0]), "r"(a[1]), "r"(a[2]), "r"(a[3]), "r"(b[0]), "r"(b[1]));
}
#define LDSM_X4(r, addr) \
    asm volatile("ldmatrix.sync.aligned.m8n8.x4.shared.b16 {%0,%1,%2,%3}, [%4];" \
                 : "=r"((r)[0]), "=r"((r)[1]), "=r"((r)[2]), "=r"((r)[3]) : "r"(addr))
#define MBAR_INIT(a, c) \
    asm volatile("mbarrier.init.shared.b64 [%0], %1;" :: "r"((uint32_t)(a)), "r"((uint32_t)(c)) : "memory")
#define MBAR_TX(a, b) \
    asm volatile("mbarrier.arrive.expect_tx.shared.b64 _, [%0], %1;" :: "r"((uint32_t)(a)), "r"((uint32_t)(b)) : "memory")
#define MBAR_WAIT(a, ph) do { \
    uint32_t _m = (uint32_t)(a), _p = (uint32_t)(ph), _d; \
    asm volatile("{\n\t.reg .pred p;\n\t" \
        "mbarrier.try_wait.parity.acquire.cta.shared::cta.b64 p, [%1], %2;\n\t" \
        "selp.b32 %0, 1, 0, p;\n\t}" : "=r"(_d) : "r"(_m), "r"(_p) : "memory"); \
    if (!_d) { \
        asm volatile("{\n\t.reg .pred P1;\n\t" \
            "WL_%=:\n\t" \
            "mbarrier.try_wait.parity.acquire.cta.shared::cta.b64 P1, [%0], %1, 0x989680;\n\t" \
            "@P1 bra.uni WD_%=;\n\t bra.uni WL_%=;\n\t WD_%=:\n\t}" \
            :: "r"(_m), "r"(_p) : "memory"); \
    } \
} while (0)
__device__ __forceinline__ void tma_bulk(uint32_t dst, const void* src, uint32_t bytes, uint32_t mbar) {
    asm volatile("cp.async.bulk.shared::cluster.global.mbarrier::complete_tx::bytes [%0], [%1], %2, [%3];"
                 :: "r"(dst), "l"(src), "r"(bytes), "r"(mbar) : "memory");
}

// ---------------------------------------------------------------------------
#define AHI_O 0
#define ALO_O (128 * ROWB)
#define BHI_O (256 * ROWB)
#define BLO_O (512 * ROWB)
#define STG (768 * ROWB)
#define MB_O (3 * STG)
#define GEMM_SMEM (3 * STG + 64)

__global__ __launch_bounds__(512, 1)
void gemm3(const uint8_t* __restrict__ Ahi, const uint8_t* __restrict__ Alo,
           const uint8_t* __restrict__ Whi, const uint8_t* __restrict__ Wlo,
           int WR, int ncb, int NSPLIT,
           float* __restrict__ outA, int ldA,
           float* __restrict__ outB, int ldB, const float* __restrict__ biasB, int M) {
    extern __shared__ char smem[];
    const uint32_t sb = smem_to_u32(smem);
    const uint32_t mb = sb + MB_O;
    const int tid = threadIdx.x, wid = tid >> 5, lane = tid & 31;
    const int wr = wid >> 2, wc = wid & 3;
    const int m0 = ((int)blockIdx.x / ncb) * 128;
    const int n0 = ((int)blockIdx.x % ncb) * 256;

    float acc[2][8][4];
#pragma unroll
    for (int i = 0; i < 2; i++)
#pragma unroll
        for (int j = 0; j < 8; j++)
#pragma unroll
            for (int k = 0; k < 4; k++) acc[i][j][k] = 0.0f;

    if (tid == 0) { MBAR_INIT(mb, 1); MBAR_INIT(mb + 8, 1); MBAR_INIT(mb + 16, 1); }
    __syncthreads();

    auto issue = [&](int c, int st) {
        uint32_t m = mb + st * 8;
        uint32_t s0 = sb + (uint32_t)st * STG;
        MBAR_TX(m, STG);
        tma_bulk(s0 + AHI_O, Ahi + ((size_t)c * MPAD + m0) * ROWB, 128 * ROWB, m);
        tma_bulk(s0 + ALO_O, Alo + ((size_t)c * MPAD + m0) * ROWB, 128 * ROWB, m);
        tma_bulk(s0 + BHI_O, Whi + ((size_t)c * WR + n0) * ROWB, 256 * ROWB, m);
        tma_bulk(s0 + BLO_O, Wlo + ((size_t)c * WR + n0) * ROWB, 256 * ROWB, m);
    };
    if (tid == 0) { issue(0, 0); issue(1, 1); }

    for (int c = 0; c < 8; c++) {
        MBAR_WAIT(mb + (c % 3) * 8, (c / 3) & 1);
        __syncthreads();
        if (tid == 0 && c + 2 < 8) issue(c + 2, (c + 2) % 3);

        const uint32_t s0 = sb + (uint32_t)(c % 3) * STG;
#pragma unroll
        for (int s = 0; s < 2; s++) {
            const uint32_t ao = s0 + (uint32_t)(wr * 32 + (lane & 15)) * ROWB + ((lane >> 4) << 4) + s * 32;
            const uint32_t bo = s0 + BHI_O + (uint32_t)(wc * 64 + (lane & 7) + ((lane >> 4) << 3)) * ROWB
                                + (((lane >> 3) & 1) << 4) + s * 32;
            uint32_t ahi[2][4], alo[2][4], bbf[4][4];
#pragma unroll
            for (int mi = 0; mi < 2; mi++) {
                LDSM_X4(ahi[mi], ao + mi * (16 * ROWB));
                LDSM_X4(alo[mi], ao + ALO_O + mi * (16 * ROWB));
            }
#pragma unroll
            for (int p = 0; p < 4; p++) LDSM_X4(bbf[p], bo + p * (16 * ROWB));
#pragma unroll
            for (int mi = 0; mi < 2; mi++)
#pragma unroll
                for (int p = 0; p < 4; p++) {
                    mma_bf16(acc[mi][2 * p], ahi[mi], &bbf[p][0]);
                    mma_bf16(acc[mi][2 * p + 1], ahi[mi], &bbf[p][2]);
                    mma_bf16(acc[mi][2 * p], alo[mi], &bbf[p][0]);
                    mma_bf16(acc[mi][2 * p + 1], alo[mi], &bbf[p][2]);
                }
#pragma unroll
            for (int p = 0; p < 4; p++) LDSM_X4(bbf[p], bo + (BLO_O - BHI_O) + p * (16 * ROWB));
#pragma unroll
            for (int mi = 0; mi < 2; mi++)
#pragma unroll
                for (int p = 0; p < 4; p++) {
                    mma_bf16(acc[mi][2 * p], ahi[mi], &bbf[p][0]);
                    mma_bf16(acc[mi][2 * p + 1], ahi[mi], &bbf[p][2]);
                }
        }
    }

    const int gc0 = n0 + wc * 64;
    const bool isB = (gc0 >= NSPLIT);
    float* out = isB ? outB : outA;
    const int ld = isB ? ldB : ldA;
    const float* bias = isB ? biasB : nullptr;
    const int cbase = gc0 - (isB ? NSPLIT : 0);
#pragma unroll
    for (int mi = 0; mi < 2; mi++) {
        int r0 = m0 + wr * 32 + mi * 16 + (lane >> 2), r1 = r0 + 8;
#pragma unroll
        for (int ni = 0; ni < 8; ni++) {
            int col = cbase + ni * 8 + 2 * (lane & 3);
            float bx = 0.f, by = 0.f;
            if (bias) { bx = __ldg(bias + col); by = __ldg(bias + col + 1); }
            if (r0 < M)
                *(float2*)(out + (size_t)r0 * ld + col) = make_float2(acc[mi][ni][0] + bx, acc[mi][ni][1] + by);
            if (r1 < M)
                *(float2*)(out + (size_t)r1 * ld + col) = make_float2(acc[mi][ni][2] + bx, acc[mi][ni][3] + by);
        }
    }
}

// ---------------------------------------------------------------------------
__device__ __forceinline__ void split1(float v, __nv_bfloat16& h, __nv_bfloat16& l) {
    h = __float2bfloat16(v);
    l = __float2bfloat16(v - __bfloat162float(h));
}
// write 4 consecutive k-elements (float4) of row m at k-quad kq4 into padded layout
__device__ __forceinline__ void store_p(uint8_t* hi, uint8_t* lo, int rows_unused,
                                        size_t rowbase, int kq4, float4 v) {
    __nv_bfloat16 h0, h1, h2, h3, l0, l1, l2, l3;
    split1(v.x, h0, l0); split1(v.y, h1, l1);
    split1(v.z, h2, l2); split1(v.w, h3, l3);
    size_t off = rowbase + (size_t)(kq4 & 7) * 8;
    *(__nv_bfloat162*)(hi + off) = __nv_bfloat162(h0, h1);
    *(__nv_bfloat162*)(hi + off + 4) = __nv_bfloat162(h2, h3);
    *(__nv_bfloat162*)(lo + off) = __nv_bfloat162(l0, l1);
    *(__nv_bfloat162*)(lo + off + 4) = __nv_bfloat162(l2, l3);
}

__global__ void qsplit_x(const float* __restrict__ in, uint8_t* __restrict__ hi,
                         uint8_t* __restrict__ lo, int M) {
    int i = blockIdx.x * blockDim.x + threadIdx.x;
    if (i >= M * 64) return;
    int m = i >> 6, kq4 = i & 63;
    int ch = kq4 >> 3;
    store_p(hi, lo, 0, ((size_t)ch * MPAD + m) * ROWB, kq4, ((const float4*)in)[i]);
}

__global__ void qsplit_w(const float* __restrict__ W1l, const float* __restrict__ W1r,
                         const float* __restrict__ W2l, const float* __restrict__ W2r) {
    int i = blockIdx.x * blockDim.x + threadIdx.x;   // 49152 float4s
    const float* src;
    uint8_t *hi, *lo;
    int row, WR;
    if (i < 32768) {      // W1 stacked 512 rows
        int b = i;
        row = b >> 6;
        src = (row < 256) ? W1l : W1r;
        int srow = row & 255;
        hi = g_w1hi; lo = g_w1lo; WR = 512;
        int kq4 = b & 63;
        float4 v = ((const float4*)src)[srow * 64 + kq4];
        store_p(hi, lo, 0, ((size_t)(kq4 >> 3) * WR + row) * ROWB, kq4, v);
    } else if (i < 49152) {  // W2 stacked 256 rows
        int b = i - 32768;
        row = b >> 6;
        src = (row < 128) ? W2l : W2r;
        int srow = (row < 128) ? row : row - 128;
        hi = g_w2hi; lo = g_w2lo; WR = 256;
        int kq4 = b & 63;
        float4 v = ((const float4*)src)[srow * 64 + kq4];
        store_p(hi, lo, 0, ((size_t)(kq4 >> 3) * WR + row) * ROWB, kq4, v);
    }
}

// ---------------------------------------------------------------------------
__global__ void deg_kernel(const int* __restrict__ dst, float* __restrict__ deg, int E) {
    int i = blockIdx.x * blockDim.x + threadIdx.x;
    if (i < E) atomicAdd(&deg[dst[i]], 1.0f);
}
__global__ void scan_part(const float* __restrict__ deg, int* __restrict__ bsum, int N) {
    __shared__ int sm[256];
    int b = blockIdx.x, t = threadIdx.x, s = 0;
#pragma unroll
    for (int k = 0; k < 4; k++) {
        int i = b * SCAN_BLK + t * 4 + k;
        if (i < N) s += (int)deg[i];
    }
    sm[t] = s; __syncthreads();
    for (int o = 128; o > 0; o >>= 1) { if (t < o) sm[t] += sm[t + o]; __syncthreads(); }
    if (t == 0) bsum[b] = sm[0];
}
__global__ void scan_sums(const int* __restrict__ bsum, int* __restrict__ boff, int nb) {
    __shared__ int sm[128];
    int t = threadIdx.x;
    sm[t] = (t < nb) ? bsum[t] : 0; __syncthreads();
    for (int o = 1; o < 128; o <<= 1) {
        int v = (t >= o) ? sm[t - o] : 0; __syncthreads();
        sm[t] += v; __syncthreads();
    }
    if (t < nb) boff[t] = (t == 0) ? 0 : sm[t - 1];
}
__global__ void scan_write(const float* __restrict__ deg, const int* __restrict__ boff,
                           int* __restrict__ rowptr, int* __restrict__ cursor, int N) {
    __shared__ int sm[256];
    int b = blockIdx.x, t = threadIdx.x, d[4], s = 0;
#pragma unroll
    for (int k = 0; k < 4; k++) {
        int i = b * SCAN_BLK + t * 4 + k;
        d[k] = (i < N) ? (int)deg[i] : 0; s += d[k];
    }
    sm[t] = s; __syncthreads();
    for (int o = 1; o < 256; o <<= 1) {
        int v = (t >= o) ? sm[t - o] : 0; __syncthreads();
        sm[t] += v; __syncthreads();
    }
    int off = boff[b] + ((t == 0) ? 0 : sm[t - 1]);
#pragma unroll
    for (int k = 0; k < 4; k++) {
        int i = b * SCAN_BLK + t * 4 + k;
        if (i < N) { rowptr[i] = off; cursor[i] = off; }
        off += d[k];
    }
}
__global__ void fill_csr(const int* __restrict__ src, const int* __restrict__ dst,
                         int* __restrict__ cursor, int* __restrict__ csr, int E) {
    int i = blockIdx.x * blockDim.x + threadIdx.x;
    if (i >= E) return;
    csr[atomicAdd(&cursor[dst[i]], 1)] = src[i];
}

// ---------------------------------------------------------------------------
__global__ void gather1(const float* __restrict__ y, const float* __restrict__ z,
                        const int* __restrict__ rowptr, const int* __restrict__ csr,
                        const float* __restrict__ deg,
                        uint8_t* __restrict__ hhi, uint8_t* __restrict__ hlo, int N) {
    int gw = (blockIdx.x * blockDim.x + threadIdx.x) >> 5;
    int lane = threadIdx.x & 31;
    int node = gw >> 1, c0 = (gw & 1) * 128;
    if (node >= N) return;
    int start = rowptr[node];
    float degf = deg[node];
    int cnt = (int)degf;
    float4 acc = make_float4(0.f, 0.f, 0.f, 0.f);
    for (int j0 = 0; j0 < cnt; j0 += 32) {
        int m = min(32, cnt - j0);
        int sid = (lane < m) ? csr[start + j0 + lane] : 0;
        for (int t = 0; t < m; t++) {
            int sN = __shfl_sync(0xffffffff, sid, t);
            float4 v = *(const float4*)(y + (size_t)sN * D1 + c0 + lane * 4);
            acc.x += v.x; acc.y += v.y; acc.z += v.z; acc.w += v.w;
        }
    }
    float sc = 1.0f / fmaxf(degf, 1.0f);
    float4 zz = *(const float4*)(z + (size_t)node * D1 + c0 + lane * 4);
    float4 r = make_float4(fmaxf(acc.x * sc + zz.x, 0.f), fmaxf(acc.y * sc + zz.y, 0.f),
                           fmaxf(acc.z * sc + zz.z, 0.f), fmaxf(acc.w * sc + zz.w, 0.f));
    int k = c0 + lane * 4;
    store_p(hhi, hlo, 0, ((size_t)(k >> 5) * MPAD + node) * ROWB, k >> 2, r);
}

__global__ void gather2(const float* __restrict__ y, const float* __restrict__ z,
                        const int* __restrict__ rowptr, const int* __restrict__ csr,
                        const float* __restrict__ deg, float* __restrict__ out, int N) {
    int node = (blockIdx.x * blockDim.x + threadIdx.x) >> 5;
    int lane = threadIdx.x & 31;
    if (node >= N) return;
    int start = rowptr[node];
    float degf = deg[node];
    int cnt = (int)degf;
    float4 acc = make_float4(0.f, 0.f, 0.f, 0.f);
    for (int j0 = 0; j0 < cnt; j0 += 32) {
        int m = min(32, cnt - j0);
        int sid = (lane < m) ? csr[start + j0 + lane] : 0;
        for (int t = 0; t < m; t++) {
            int sN = __shfl_sync(0xffffffff, sid, t);
            float4 v = *(const float4*)(y + (size_t)sN * D2 + lane * 4);
            acc.x += v.x; acc.y += v.y; acc.z += v.z; acc.w += v.w;
        }
    }
    float sc = 1.0f / fmaxf(degf, 1.0f);
    float4 zz = *(const float4*)(z + (size_t)node * D2 + lane * 4);
    *(float4*)(out + (size_t)node * D2 + lane * 4) =
        make_float4(acc.x * sc + zz.x, acc.y * sc + zz.y, acc.z * sc + zz.z, acc.w * sc + zz.w);
}

// ---------------------------------------------------------------------------
extern "C" void kernel_launch(void* const* d_in, const int* in_sizes, int n_in,
                              void* d_out, int out_size) {
    const float* x   = (const float*)d_in[0];
    const int* eidx  = (const int*)d_in[1];
    const float* W1l = (const float*)d_in[2];
    const float* b1  = (const float*)d_in[3];
    const float* W1r = (const float*)d_in[4];
    const float* W2l = (const float*)d_in[5];
    const float* b2  = (const float*)d_in[6];
    const float* W2r = (const float*)d_in[7];
    float* out = (float*)d_out;

    const int N = in_sizes[0] / D1;
    const int E = in_sizes[1] / 2;
    const int* src = eidx;
    const int* dst = eidx + E;

    float *y1, *z1, *y2, *z2, *deg;
    uint8_t *xhi, *xlo, *hhi, *hlo, *w1hi, *w1lo, *w2hi, *w2lo;
    int *rowptr, *cursor, *csr, *bsum, *boff;
    cudaGetSymbolAddress((void**)&y1, g_y1);
    cudaGetSymbolAddress((void**)&z1, g_z1);
    cudaGetSymbolAddress((void**)&y2, g_y2);
    cudaGetSymbolAddress((void**)&z2, g_z2);
    cudaGetSymbolAddress((void**)&deg, g_deg);
    cudaGetSymbolAddress((void**)&xhi, g_xhi);
    cudaGetSymbolAddress((void**)&xlo, g_xlo);
    cudaGetSymbolAddress((void**)&hhi, g_hhi);
    cudaGetSymbolAddress((void**)&hlo, g_hlo);
    cudaGetSymbolAddress((void**)&w1hi, g_w1hi);
    cudaGetSymbolAddress((void**)&w1lo, g_w1lo);
    cudaGetSymbolAddress((void**)&w2hi, g_w2hi);
    cudaGetSymbolAddress((void**)&w2lo, g_w2lo);
    cudaGetSymbolAddress((void**)&rowptr, g_rowptr);
    cudaGetSymbolAddress((void**)&cursor, g_cursor);
    cudaGetSymbolAddress((void**)&csr, g_csr);
    cudaGetSymbolAddress((void**)&bsum, g_bsum);
    cudaGetSymbolAddress((void**)&boff, g_boff);

    cudaFuncSetAttribute(gemm3, cudaFuncAttributeMaxDynamicSharedMemorySize, GEMM_SMEM);

    const int mb = (N + 127) / 128;
    const int nb = (N + SCAN_BLK - 1) / SCAN_BLK;

    cudaMemsetAsync(deg, 0, (size_t)N * sizeof(float));
    deg_kernel<<<(E + 255) / 256, 256>>>(dst, deg, E);                           // k1
    qsplit_x<<<(N * 64 + 255) / 256, 256>>>(x, xhi, xlo, N);                     // k2
    qsplit_w<<<(49152 + 255) / 256, 256>>>(W1l, W1r, W2l, W2r);                  // k3
    // k4 ← profiled: layer-1 fused y1|z1 (stacked W1, 512 rows, ncb=2)
    gemm3<<<2 * mb, 512, GEMM_SMEM>>>(xhi, xlo, w1hi, w1lo, 512, 2, 256,
                                      y1, D1, z1, D1, b1, N);                    // k4
    scan_part<<<nb, 256>>>(deg, bsum, N);                                        // k5
    scan_sums<<<1, 128>>>(bsum, boff, nb);                                       // k6
    scan_write<<<nb, 256>>>(deg, boff, rowptr, cursor, N);                       // k7
    fill_csr<<<(E + 255) / 256, 256>>>(src, dst, cursor, csr, E);                // k8
    gather1<<<(2 * N * 32 + 255) / 256, 256>>>(y1, z1, rowptr, csr, deg, hhi, hlo, N); // k9
    gemm3<<<mb, 512, GEMM_SMEM>>>(hhi, hlo, w2hi, w2lo, 256, 1, 128,
                                  y2, D2, z2, D2, b2, N);                        // k10
    gather2<<<(N * 32 + 255) / 256, 256>>>(y2, z2, rowptr, csr, deg, out, N);    // k11
}

// round 11
// speedup vs baseline: 1.3029x; 1.2020x over previous
#include <cuda_runtime.h>
#include <cuda_bf16.h>
#include <cstdint>

#define D1 256
#define D2 128
#define K_DIM 256
#define ROWB 80
#define MPAD 100096

static const int MAX_N = 100000;
static const int MAX_E = 1600000;

__device__ __nv_bfloat16 g_y1[MAX_N * D1];
__device__ float g_z1[MAX_N * D1];
__device__ __nv_bfloat16 g_y2[MAX_N * D2];
__device__ float g_z2[MAX_N * D2];
__device__ float g_deg[MAX_N];
// chunk-major padded splits: [8][MPAD][80B]
__device__ uint8_t g_xhi[8ull * MPAD * ROWB];
__device__ uint8_t g_xlo[8ull * MPAD * ROWB];
__device__ uint8_t g_hhi[8ull * MPAD * ROWB];
__device__ uint8_t g_hlo[8ull * MPAD * ROWB];
__device__ uint8_t g_w1hi[8 * 512 * ROWB];
__device__ uint8_t g_w1lo[8 * 512 * ROWB];
__device__ uint8_t g_w2hi[8 * 256 * ROWB];
__device__ uint8_t g_w2lo[8 * 256 * ROWB];
__device__ int g_rowptr[MAX_N];
__device__ int g_cursor[MAX_N];
__device__ int g_csr[MAX_E];
__device__ int g_bsum[128];
__device__ int g_boff[128];

#define SCAN_BLK 1024

__device__ __forceinline__ uint32_t smem_to_u32(const void* p) {
    uint32_t a;
    asm("{ .reg .u64 t; cvta.to.shared.u64 t, %1; cvt.u32.u64 %0, t; }" : "=r"(a) : "l"(p));
    return a;
}
__device__ __forceinline__ void mma_bf16(float* c, const uint32_t* a, const uint32_t* b) {
    asm volatile("mma.sync.aligned.m16n8k16.row.col.f32.bf16.bf16.f32 "
                 "{%0,%1,%2,%3}, {%4,%5,%6,%7}, {%8,%9}, {%0,%1,%2,%3};"
                 : "+f"(c[0]), "+f"(c[1]), "+f"(c[2]), "+f"(c[3])
                 : "r"(a[0]), "r"(a[1]), "r"(a[2]), "r"(a[3]), "r"(b[0]), "r"(b[1]));
}
#define LDSM_X4(r, addr) \
    asm volatile("ldmatrix.sync.aligned.m8n8.x4.shared.b16 {%0,%1,%2,%3}, [%4];" \
                 : "=r"((r)[0]), "=r"((r)[1]), "=r"((r)[2]), "=r"((r)[3]) : "r"(addr))
#define MBAR_INIT(a, c) \
    asm volatile("mbarrier.init.shared.b64 [%0], %1;" :: "r"((uint32_t)(a)), "r"((uint32_t)(c)) : "memory")
#define MBAR_TX(a, b) \
    asm volatile("mbarrier.arrive.expect_tx.shared.b64 _, [%0], %1;" :: "r"((uint32_t)(a)), "r"((uint32_t)(b)) : "memory")
#define MBAR_WAIT(a, ph) do { \
    uint32_t _m = (uint32_t)(a), _p = (uint32_t)(ph), _d; \
    asm volatile("{\n\t.reg .pred p;\n\t" \
        "mbarrier.try_wait.parity.acquire.cta.shared::cta.b64 p, [%1], %2;\n\t" \
        "selp.b32 %0, 1, 0, p;\n\t}" : "=r"(_d) : "r"(_m), "r"(_p) : "memory"); \
    if (!_d) { \
        asm volatile("{\n\t.reg .pred P1;\n\t" \
            "WL_%=:\n\t" \
            "mbarrier.try_wait.parity.acquire.cta.shared::cta.b64 P1, [%0], %1, 0x989680;\n\t" \
            "@P1 bra.uni WD_%=;\n\t bra.uni WL_%=;\n\t WD_%=:\n\t}" \
            :: "r"(_m), "r"(_p) : "memory"); \
    } \
} while (0)
__device__ __forceinline__ void tma_bulk(uint32_t dst, const void* src, uint32_t bytes, uint32_t mbar) {
    asm volatile("cp.async.bulk.shared::cluster.global.mbarrier::complete_tx::bytes [%0], [%1], %2, [%3];"
                 :: "r"(dst), "l"(src), "r"(bytes), "r"(mbar) : "memory");
}

// ---------------------------------------------------------------------------
#define AHI_O 0
#define ALO_O (128 * ROWB)
#define BHI_O (256 * ROWB)
#define BLO_O (512 * ROWB)
#define STG (768 * ROWB)
#define MB_O (3 * STG)
#define GEMM_SMEM (3 * STG + 64)

// y path (cols < NSPLIT) -> outY (bf16); z path -> outZ (fp32, +bias)
__global__ __launch_bounds__(512, 1)
void gemm3(const uint8_t* __restrict__ Ahi, const uint8_t* __restrict__ Alo,
           const uint8_t* __restrict__ Whi, const uint8_t* __restrict__ Wlo,
           int WR, int ncb, int NSPLIT,
           __nv_bfloat16* __restrict__ outY, int ldY,
           float* __restrict__ outZ, int ldZ, const float* __restrict__ biasZ, int M) {
    extern __shared__ char smem[];
    const uint32_t sb = smem_to_u32(smem);
    const uint32_t mb = sb + MB_O;
    const int tid = threadIdx.x, wid = tid >> 5, lane = tid & 31;
    const int wr = wid >> 2, wc = wid & 3;
    const int m0 = ((int)blockIdx.x / ncb) * 128;
    const int n0 = ((int)blockIdx.x % ncb) * 256;

    float acc[2][8][4];
#pragma unroll
    for (int i = 0; i < 2; i++)
#pragma unroll
        for (int j = 0; j < 8; j++)
#pragma unroll
            for (int k = 0; k < 4; k++) acc[i][j][k] = 0.0f;

    if (tid == 0) { MBAR_INIT(mb, 1); MBAR_INIT(mb + 8, 1); MBAR_INIT(mb + 16, 1); }
    __syncthreads();

    auto issue = [&](int c, int st) {
        uint32_t m = mb + st * 8;
        uint32_t s0 = sb + (uint32_t)st * STG;
        MBAR_TX(m, STG);
        tma_bulk(s0 + AHI_O, Ahi + ((size_t)c * MPAD + m0) * ROWB, 128 * ROWB, m);
        tma_bulk(s0 + ALO_O, Alo + ((size_t)c * MPAD + m0) * ROWB, 128 * ROWB, m);
        tma_bulk(s0 + BHI_O, Whi + ((size_t)c * WR + n0) * ROWB, 256 * ROWB, m);
        tma_bulk(s0 + BLO_O, Wlo + ((size_t)c * WR + n0) * ROWB, 256 * ROWB, m);
    };
    if (tid == 0) { issue(0, 0); issue(1, 1); }

    for (int c = 0; c < 8; c++) {
        MBAR_WAIT(mb + (c % 3) * 8, (c / 3) & 1);
        __syncthreads();
        if (tid == 0 && c + 2 < 8) issue(c + 2, (c + 2) % 3);

        const uint32_t s0 = sb + (uint32_t)(c % 3) * STG;
#pragma unroll
        for (int s = 0; s < 2; s++) {
            const uint32_t ao = s0 + (uint32_t)(wr * 32 + (lane & 15)) * ROWB + ((lane >> 4) << 4) + s * 32;
            const uint32_t bo = s0 + BHI_O + (uint32_t)(wc * 64 + (lane & 7) + ((lane >> 4) << 3)) * ROWB
                                + (((lane >> 3) & 1) << 4) + s * 32;
            uint32_t ahi[2][4], alo[2][4], bbf[4][4];
#pragma unroll
            for (int mi = 0; mi < 2; mi++) {
                LDSM_X4(ahi[mi], ao + mi * (16 * ROWB));
                LDSM_X4(alo[mi], ao + ALO_O + mi * (16 * ROWB));
            }
#pragma unroll
            for (int p = 0; p < 4; p++) LDSM_X4(bbf[p], bo + p * (16 * ROWB));
#pragma unroll
            for (int mi = 0; mi < 2; mi++)
#pragma unroll
                for (int p = 0; p < 4; p++) {
                    mma_bf16(acc[mi][2 * p], ahi[mi], &bbf[p][0]);
                    mma_bf16(acc[mi][2 * p + 1], ahi[mi], &bbf[p][2]);
                    mma_bf16(acc[mi][2 * p], alo[mi], &bbf[p][0]);
                    mma_bf16(acc[mi][2 * p + 1], alo[mi], &bbf[p][2]);
                }
#pragma unroll
            for (int p = 0; p < 4; p++) LDSM_X4(bbf[p], bo + (BLO_O - BHI_O) + p * (16 * ROWB));
#pragma unroll
            for (int mi = 0; mi < 2; mi++)
#pragma unroll
                for (int p = 0; p < 4; p++) {
                    mma_bf16(acc[mi][2 * p], ahi[mi], &bbf[p][0]);
                    mma_bf16(acc[mi][2 * p + 1], ahi[mi], &bbf[p][2]);
                }
        }
    }

    const int gc0 = n0 + wc * 64;
    if (gc0 >= NSPLIT) {
        // z path: fp32 + bias
        const int cbase = gc0 - NSPLIT;
#pragma unroll
        for (int mi = 0; mi < 2; mi++) {
            int r0 = m0 + wr * 32 + mi * 16 + (lane >> 2), r1 = r0 + 8;
#pragma unroll
            for (int ni = 0; ni < 8; ni++) {
                int col = cbase + ni * 8 + 2 * (lane & 3);
                float bx = __ldg(biasZ + col), by = __ldg(biasZ + col + 1);
                if (r0 < M)
                    *(float2*)(outZ + (size_t)r0 * ldZ + col) = make_float2(acc[mi][ni][0] + bx, acc[mi][ni][1] + by);
                if (r1 < M)
                    *(float2*)(outZ + (size_t)r1 * ldZ + col) = make_float2(acc[mi][ni][2] + bx, acc[mi][ni][3] + by);
            }
        }
    } else {
        // y path: bf16
#pragma unroll
        for (int mi = 0; mi < 2; mi++) {
            int r0 = m0 + wr * 32 + mi * 16 + (lane >> 2), r1 = r0 + 8;
#pragma unroll
            for (int ni = 0; ni < 8; ni++) {
                int col = gc0 + ni * 8 + 2 * (lane & 3);
                if (r0 < M)
                    *(__nv_bfloat162*)(outY + (size_t)r0 * ldY + col) =
                        __nv_bfloat162(__float2bfloat16(acc[mi][ni][0]), __float2bfloat16(acc[mi][ni][1]));
                if (r1 < M)
                    *(__nv_bfloat162*)(outY + (size_t)r1 * ldY + col) =
                        __nv_bfloat162(__float2bfloat16(acc[mi][ni][2]), __float2bfloat16(acc[mi][ni][3]));
            }
        }
    }
}

// ---------------------------------------------------------------------------
__device__ __forceinline__ void split1(float v, __nv_bfloat16& h, __nv_bfloat16& l) {
    h = __float2bfloat16(v);
    l = __float2bfloat16(v - __bfloat162float(h));
}
__device__ __forceinline__ void store_p(uint8_t* hi, uint8_t* lo, size_t rowbase, int kq4, float4 v) {
    __nv_bfloat16 h0, h1, h2, h3, l0, l1, l2, l3;
    split1(v.x, h0, l0); split1(v.y, h1, l1);
    split1(v.z, h2, l2); split1(v.w, h3, l3);
    size_t off = rowbase + (size_t)(kq4 & 7) * 8;
    *(__nv_bfloat162*)(hi + off) = __nv_bfloat162(h0, h1);
    *(__nv_bfloat162*)(hi + off + 4) = __nv_bfloat162(h2, h3);
    *(__nv_bfloat162*)(lo + off) = __nv_bfloat162(l0, l1);
    *(__nv_bfloat162*)(lo + off + 4) = __nv_bfloat162(l2, l3);
}

__global__ void qsplit_x(const float* __restrict__ in, uint8_t* __restrict__ hi,
                         uint8_t* __restrict__ lo, int M) {
    int i = blockIdx.x * blockDim.x + threadIdx.x;
    if (i >= M * 64) return;
    int m = i >> 6, kq4 = i & 63;
    store_p(hi, lo, ((size_t)(kq4 >> 3) * MPAD + m) * ROWB, kq4, ((const float4*)in)[i]);
}

__global__ void qsplit_w(const float* __restrict__ W1l, const float* __restrict__ W1r,
                         const float* __restrict__ W2l, const float* __restrict__ W2r) {
    int i = blockIdx.x * blockDim.x + threadIdx.x;
    if (i < 32768) {
        int row = i >> 6, kq4 = i & 63;
        const float* src = (row < 256) ? W1l : W1r;
        float4 v = ((const float4*)src)[(row & 255) * 64 + kq4];
        store_p(g_w1hi, g_w1lo, ((size_t)(kq4 >> 3) * 512 + row) * ROWB, kq4, v);
    } else if (i < 49152) {
        int b = i - 32768;
        int row = b >> 6, kq4 = b & 63;
        const float* src = (row < 128) ? W2l : W2r;
        int srow = (row < 128) ? row : row - 128;
        float4 v = ((const float4*)src)[srow * 64 + kq4];
        store_p(g_w2hi, g_w2lo, ((size_t)(kq4 >> 3) * 256 + row) * ROWB, kq4, v);
    }
}

// ---------------------------------------------------------------------------
__global__ void deg_kernel(const int* __restrict__ dst, float* __restrict__ deg, int E) {
    int i = blockIdx.x * blockDim.x + threadIdx.x;
    if (i < E) atomicAdd(&deg[dst[i]], 1.0f);
}
__global__ void scan_part(const float* __restrict__ deg, int* __restrict__ bsum, int N) {
    __shared__ int sm[256];
    int b = blockIdx.x, t = threadIdx.x, s = 0;
#pragma unroll
    for (int k = 0; k < 4; k++) {
        int i = b * SCAN_BLK + t * 4 + k;
        if (i < N) s += (int)deg[i];
    }
    sm[t] = s; __syncthreads();
    for (int o = 128; o > 0; o >>= 1) { if (t < o) sm[t] += sm[t + o]; __syncthreads(); }
    if (t == 0) bsum[b] = sm[0];
}
__global__ void scan_sums(const int* __restrict__ bsum, int* __restrict__ boff, int nb) {
    __shared__ int sm[128];
    int t = threadIdx.x;
    sm[t] = (t < nb) ? bsum[t] : 0; __syncthreads();
    for (int o = 1; o < 128; o <<= 1) {
        int v = (t >= o) ? sm[t - o] : 0; __syncthreads();
        sm[t] += v; __syncthreads();
    }
    if (t < nb) boff[t] = (t == 0) ? 0 : sm[t - 1];
}
__global__ void scan_write(const float* __restrict__ deg, const int* __restrict__ boff,
                           int* __restrict__ rowptr, int* __restrict__ cursor, int N) {
    __shared__ int sm[256];
    int b = blockIdx.x, t = threadIdx.x, d[4], s = 0;
#pragma unroll
    for (int k = 0; k < 4; k++) {
        int i = b * SCAN_BLK + t * 4 + k;
        d[k] = (i < N) ? (int)deg[i] : 0; s += d[k];
    }
    sm[t] = s; __syncthreads();
    for (int o = 1; o < 256; o <<= 1) {
        int v = (t >= o) ? sm[t - o] : 0; __syncthreads();
        sm[t] += v; __syncthreads();
    }
    int off = boff[b] + ((t == 0) ? 0 : sm[t - 1]);
#pragma unroll
    for (int k = 0; k < 4; k++) {
        int i = b * SCAN_BLK + t * 4 + k;
        if (i < N) { rowptr[i] = off; cursor[i] = off; }
        off += d[k];
    }
}
__global__ void fill_csr(const int* __restrict__ src, const int* __restrict__ dst,
                         int* __restrict__ cursor, int* __restrict__ csr, int E) {
    int i = blockIdx.x * blockDim.x + threadIdx.x;
    if (i >= E) return;
    csr[atomicAdd(&cursor[dst[i]], 1)] = src[i];
}

// ---------------------------------------------------------------------------
__device__ __forceinline__ float4 bf16x4_load(const __nv_bfloat16* p) {
    uint2 raw = *(const uint2*)p;
    __nv_bfloat162 a = *reinterpret_cast<__nv_bfloat162*>(&raw.x);
    __nv_bfloat162 b = *reinterpret_cast<__nv_bfloat162*>(&raw.y);
    float2 f0 = __bfloat1622float2(a), f1 = __bfloat1622float2(b);
    return make_float4(f0.x, f0.y, f1.x, f1.y);
}

__global__ void gather1(const __nv_bfloat16* __restrict__ y, const float* __restrict__ z,
                        const int* __restrict__ rowptr, const int* __restrict__ csr,
                        const float* __restrict__ deg,
                        uint8_t* __restrict__ hhi, uint8_t* __restrict__ hlo, int N) {
    int gw = (blockIdx.x * blockDim.x + threadIdx.x) >> 5;
    int lane = threadIdx.x & 31;
    int node = gw >> 1, c0 = (gw & 1) * 128;
    if (node >= N) return;
    int start = rowptr[node];
    float degf = deg[node];
    int cnt = (int)degf;
    float4 acc = make_float4(0.f, 0.f, 0.f, 0.f);
    for (int j0 = 0; j0 < cnt; j0 += 32) {
        int m = min(32, cnt - j0);
        int sid = (lane < m) ? csr[start + j0 + lane] : 0;
        for (int t = 0; t < m; t++) {
            int sN = __shfl_sync(0xffffffff, sid, t);
            float4 v = bf16x4_load(y + (size_t)sN * D1 + c0 + lane * 4);
            acc.x += v.x; acc.y += v.y; acc.z += v.z; acc.w += v.w;
        }
    }
    float sc = 1.0f / fmaxf(degf, 1.0f);
    float4 zz = *(const float4*)(z + (size_t)node * D1 + c0 + lane * 4);
    float4 r = make_float4(fmaxf(acc.x * sc + zz.x, 0.f), fmaxf(acc.y * sc + zz.y, 0.f),
                           fmaxf(acc.z * sc + zz.z, 0.f), fmaxf(acc.w * sc + zz.w, 0.f));
    int k = c0 + lane * 4;
    store_p(hhi, hlo, ((size_t)(k >> 5) * MPAD + node) * ROWB, k >> 2, r);
}

__global__ void gather2(const __nv_bfloat16* __restrict__ y, const float* __restrict__ z,
                        const int* __restrict__ rowptr, const int* __restrict__ csr,
                        const float* __restrict__ deg, float* __restrict__ out, int N) {
    int node = (blockIdx.x * blockDim.x + threadIdx.x) >> 5;
    int lane = threadIdx.x & 31;
    if (node >= N) return;
    int start = rowptr[node];
    float degf = deg[node];
    int cnt = (int)degf;
    float4 acc = make_float4(0.f, 0.f, 0.f, 0.f);
    for (int j0 = 0; j0 < cnt; j0 += 32) {
        int m = min(32, cnt - j0);
        int sid = (lane < m) ? csr[start + j0 + lane] : 0;
        for (int t = 0; t < m; t++) {
            int sN = __shfl_sync(0xffffffff, sid, t);
            float4 v = bf16x4_load(y + (size_t)sN * D2 + lane * 4);
            acc.x += v.x; acc.y += v.y; acc.z += v.z; acc.w += v.w;
        }
    }
    float sc = 1.0f / fmaxf(degf, 1.0f);
    float4 zz = *(const float4*)(z + (size_t)node * D2 + lane * 4);
    *(float4*)(out + (size_t)node * D2 + lane * 4) =
        make_float4(acc.x * sc + zz.x, acc.y * sc + zz.y, acc.z * sc + zz.z, acc.w * sc + zz.w);
}

// ---------------------------------------------------------------------------
extern "C" void kernel_launch(void* const* d_in, const int* in_sizes, int n_in,
                              void* d_out, int out_size) {
    const float* x   = (const float*)d_in[0];
    const int* eidx  = (const int*)d_in[1];
    const float* W1l = (const float*)d_in[2];
    const float* b1  = (const float*)d_in[3];
    const float* W1r = (const float*)d_in[4];
    const float* W2l = (const float*)d_in[5];
    const float* b2  = (const float*)d_in[6];
    const float* W2r = (const float*)d_in[7];
    float* out = (float*)d_out;

    const int N = in_sizes[0] / D1;
    const int E = in_sizes[1] / 2;
    const int* src = eidx;
    const int* dst = eidx + E;

    __nv_bfloat16 *y1, *y2;
    float *z1, *z2, *deg;
    uint8_t *xhi, *xlo, *hhi, *hlo, *w1hi, *w1lo, *w2hi, *w2lo;
    int *rowptr, *cursor, *csr, *bsum, *boff;
    cudaGetSymbolAddress((void**)&y1, g_y1);
    cudaGetSymbolAddress((void**)&z1, g_z1);
    cudaGetSymbolAddress((void**)&y2, g_y2);
    cudaGetSymbolAddress((void**)&z2, g_z2);
    cudaGetSymbolAddress((void**)&deg, g_deg);
    cudaGetSymbolAddress((void**)&xhi, g_xhi);
    cudaGetSymbolAddress((void**)&xlo, g_xlo);
    cudaGetSymbolAddress((void**)&hhi, g_hhi);
    cudaGetSymbolAddress((void**)&hlo, g_hlo);
    cudaGetSymbolAddress((void**)&w1hi, g_w1hi);
    cudaGetSymbolAddress((void**)&w1lo, g_w1lo);
    cudaGetSymbolAddress((void**)&w2hi, g_w2hi);
    cudaGetSymbolAddress((void**)&w2lo, g_w2lo);
    cudaGetSymbolAddress((void**)&rowptr, g_rowptr);
    cudaGetSymbolAddress((void**)&cursor, g_cursor);
    cudaGetSymbolAddress((void**)&csr, g_csr);
    cudaGetSymbolAddress((void**)&bsum, g_bsum);
    cudaGetSymbolAddress((void**)&boff, g_boff);

    cudaFuncSetAttribute(gemm3, cudaFuncAttributeMaxDynamicSharedMemorySize, GEMM_SMEM);

    const int mb = (N + 127) / 128;
    const int nb = (N + SCAN_BLK - 1) / SCAN_BLK;

    // fork a side stream for the CSR chain (independent of GEMM inputs)
    cudaStream_t s2;
    cudaStreamCreateWithFlags(&s2, cudaStreamNonBlocking);
    cudaEvent_t evFork, evJoin;
    cudaEventCreateWithFlags(&evFork, cudaEventDisableTiming);
    cudaEventCreateWithFlags(&evJoin, cudaEventDisableTiming);

    cudaEventRecord(evFork, 0);
    cudaStreamWaitEvent(s2, evFork, 0);
    // side chain: degree + CSR build
    cudaMemsetAsync(deg, 0, (size_t)N * sizeof(float), s2);
    deg_kernel<<<(E + 255) / 256, 256, 0, s2>>>(dst, deg, E);
    scan_part<<<nb, 256, 0, s2>>>(deg, bsum, N);
    scan_sums<<<1, 128, 0, s2>>>(bsum, boff, nb);
    scan_write<<<nb, 256, 0, s2>>>(deg, boff, rowptr, cursor, N);
    fill_csr<<<(E + 255) / 256, 256, 0, s2>>>(src, dst, cursor, csr, E);
    cudaEventRecord(evJoin, s2);

    // main chain
    qsplit_x<<<(N * 64 + 255) / 256, 256>>>(x, xhi, xlo, N);
    qsplit_w<<<(49152 + 255) / 256, 256>>>(W1l, W1r, W2l, W2r);
    gemm3<<<2 * mb, 512, GEMM_SMEM>>>(xhi, xlo, w1hi, w1lo, 512, 2, 256,
                                      y1, D1, z1, D1, b1, N);
    cudaStreamWaitEvent(0, evJoin, 0);
    gather1<<<(2 * N * 32 + 255) / 256, 256>>>(y1, z1, rowptr, csr, deg, hhi, hlo, N);
    gemm3<<<mb, 512, GEMM_SMEM>>>(hhi, hlo, w2hi, w2lo, 256, 1, 128,
                                  y2, D2, z2, D2, b2, N);
    gather2<<<(N * 32 + 255) / 256, 256>>>(y2, z2, rowptr, csr, deg, out, N);

    cudaEventDestroy(evFork);
    cudaEventDestroy(evJoin);
    cudaStreamDestroy(s2);
}